// round 11
// baseline (speedup 1.0000x reference)
#include <cuda_runtime.h>
#include <cuda_fp16.h>
#include <cstdint>
#include <math.h>

#define Bdim 64
#define Idim 2048
#define Hdim 2048
#define Tdim 128
#define Mtot (Tdim * Bdim)          // 8192 rows (t,b)
#define OVF_CAP 4096

// ---------------- scratch (device globals; allocation-free) ----------------
__device__ __half g_Ah[(size_t)Mtot * Idim];          // 32 MB dense A (fallback)
__device__ __half g_Ac[(size_t)Mtot * 1024];          // 16 MB compressed A (2:4)
__device__ unsigned g_meta[(size_t)Mtot * 64];        // 2 MB  metadata words
__device__ __half g_w0[(size_t)Hdim * Idim];          // 8 MB  hi plane [h][i]
__device__ __half g_w1[(size_t)Hdim * Idim];          // 8 MB  res*2^11 [h][i]
__device__ float  g_wfix[(size_t)Idim * Hdim];        // 16 MB w_eff [i][h] (fixup)
__device__ float  g_weightedT[(size_t)Tdim * Hdim * Bdim];  // 64 MB [t][h][b]
__device__ int    g_ovf_cnt[64];
__device__ int    g_ovf[64 * OVF_CAP];                // (m&127)<<16 | i
__device__ int    g_fail;

// ---------------------------------------------------------------------------
__global__ void reset_kernel() {
    if (threadIdx.x < 64) g_ovf_cnt[threadIdx.x] = 0;
    if (threadIdx.x == 64) g_fail = 0;
}

// ---------------------------------------------------------------------------
// Fused prep: blocks [0,16384): spike transpose + dense A + 2:4 compression;
//             blocks [16384,20480): weight split (+ fp32 [i][h] copy).
// ---------------------------------------------------------------------------
__global__ void prep_kernel(const float* __restrict__ in,
                            const float* __restrict__ w,
                            const float* __restrict__ s) {
    __shared__ float tile[32][33];
    int bid = blockIdx.x;
    int tx = threadIdx.x, ty = threadIdx.y;

    if (bid < 16384) {
        int t0 = (bid & 3) * 32;
        int i0 = ((bid >> 2) & 63) * 32;
        int b  = bid >> 8;
#pragma unroll
        for (int j = 0; j < 32; j += 8)
            tile[ty + j][tx] = in[((size_t)b * Idim + i0 + ty + j) * Tdim + t0 + tx];
        __syncthreads();
#pragma unroll
        for (int j = 0; j < 32; j += 8)
            g_Ah[((size_t)(t0 + ty + j) * Bdim + b) * Idim + i0 + tx] =
                __float2half_rn(tile[tx][ty + j]);

        // 2:4 compression: thread tx (ty==0) handles row m=(t0+tx)*64+b, window i0/32
        if (ty == 0) {
            int m = (t0 + tx) * Bdim + b;
            int blk = m >> 7;
            unsigned meta = 0;
            __half vals[16];
#pragma unroll
            for (int j = 0; j < 8; j++) {
                int n = 0, id0 = 0, id1 = 1;
                float v0f = 0.0f, v1f = 0.0f;
#pragma unroll
                for (int c = 0; c < 4; c++) {
                    float v = tile[j * 4 + c][tx];
                    if (v != 0.0f) {
                        if (n == 0)      { id0 = c; v0f = v; n = 1; }
                        else if (n == 1) { id1 = c; v1f = v; n = 2; }
                        else {
                            int pos = atomicAdd(&g_ovf_cnt[blk], 1);
                            if (pos < OVF_CAP)
                                g_ovf[blk * OVF_CAP + pos] =
                                    ((m & 127) << 16) | (i0 + j * 4 + c);
                        }
                    }
                }
                if (n == 0)      { id0 = 0; id1 = 1; }
                else if (n == 1) {
                    if (id0 == 3) { id0 = 0; id1 = 3; v1f = v0f; v0f = 0.0f; }
                    else          { id1 = 3; v1f = 0.0f; }
                }
                meta |= (unsigned)(id0 | (id1 << 2)) << (4 * j);
                vals[j * 2]     = __float2half_rn(v0f);
                vals[j * 2 + 1] = __float2half_rn(v1f);
            }
            int wdx = i0 >> 5;
            g_meta[(size_t)m * 64 + wdx] = meta;
            *reinterpret_cast<uint4*>(g_Ac + (size_t)m * 1024 + wdx * 16)
                = *reinterpret_cast<uint4*>(vals);
            *reinterpret_cast<uint4*>(g_Ac + (size_t)m * 1024 + wdx * 16 + 8)
                = *reinterpret_cast<uint4*>(vals + 8);
        }
    } else {
        int sid = bid - 16384;
        int i0 = (sid & 63) * 32;
        int h0 = (sid >> 6) * 32;
#pragma unroll
        for (int j = 0; j < 32; j += 8) {
            size_t idx = (size_t)(i0 + ty + j) * Hdim + h0 + tx;
            float v = w[idx] * s[idx];
            tile[ty + j][tx] = v;
            g_wfix[idx] = v;
        }
        __syncthreads();
#pragma unroll
        for (int j = 0; j < 32; j += 8) {
            float v = tile[tx][ty + j];                 // [i=tx][h=ty+j]
            __half hi = __float2half_rn(v);
            float r = v - __half2float(hi);             // exact (Fast2Sum)
            __half lo = __float2half_rn(r * 2048.0f);
            size_t o = (size_t)(h0 + ty + j) * Idim + i0 + tx;
            g_w0[o] = hi;
            g_w1[o] = lo;
        }
    }
}

// ---------------------------------------------------------------------------
// Shared GEMM constants
// ---------------------------------------------------------------------------
#define BM 128
#define BN 128
#define EPI_STR 65
#define NKT 64

__device__ __forceinline__ void ldsm_x4(uint32_t* r, uint32_t addr) {
    asm volatile("ldmatrix.sync.aligned.m8n8.x4.shared.b16 {%0,%1,%2,%3}, [%4];"
                 : "=r"(r[0]), "=r"(r[1]), "=r"(r[2]), "=r"(r[3]) : "r"(addr));
}

// ---------------------------------------------------------------------------
// SPARSE GEMM: mma.sp::ordered_metadata m16n8k32, compressed A + dense B.
// CTA 128x128, 256 threads (8 warps, warp tile 32x64), 3-stage cp.async.
// Per kt: logical BK=64 = two k32 sp-mmas per (mt,nt). Fixup adds dropped
// spikes (2:4 violations) from g_ovf into the accumulators.
// ---------------------------------------------------------------------------
#define SP_ASTR 40                           // halves per compressed-A row (80B)
#define SP_BSTR 72                           // halves per B row (144B)
#define SP_A_BYTES (128 * 80)                // 10240
#define SP_B_BYTES (128 * 144)               // 18432
#define SP_M_BYTES (128 * 8)                 // 1024
#define SP_STAGE (SP_A_BYTES + SP_B_BYTES + SP_M_BYTES)   // 29696
#define SP_SMEM (3 * SP_STAGE)                            // 89088

__device__ __forceinline__ void stage_load_sp(uint32_t sbase, int stage, int kt,
                                              int tid, int m0, int n0) {
    const __half* Bsrc = (kt < 32 ? g_w1 : g_w0) + (size_t)n0 * Idim;
    int kk = kt & 31;
    uint32_t sA = sbase + (uint32_t)stage * SP_STAGE;
    uint32_t sB = sA + SP_A_BYTES;
    uint32_t sM = sB + SP_B_BYTES;
#pragma unroll
    for (int i = 0; i < 2; i++) {            // Ac: 128 rows x 64B
        int ch = tid + i * 256;
        int r = ch >> 2, c = ch & 3;
        uint32_t d = sA + (uint32_t)(r * 80 + c * 16);
        asm volatile("cp.async.cg.shared.global [%0], [%1], 16;"
                     :: "r"(d), "l"(g_Ac + (size_t)(m0 + r) * 1024 + kk * 32 + c * 8));
    }
#pragma unroll
    for (int i = 0; i < 4; i++) {            // B: 128 rows x 128B
        int ch = tid + i * 256;
        int r = ch >> 3, c = ch & 7;
        uint32_t d = sB + (uint32_t)(r * 144 + c * 16);
        asm volatile("cp.async.cg.shared.global [%0], [%1], 16;"
                     :: "r"(d), "l"(Bsrc + (size_t)r * Idim + kk * 64 + c * 8));
    }
    if (tid < 128) {                         // meta: 128 rows x 8B
        uint32_t d = sM + (uint32_t)tid * 8;
        asm volatile("cp.async.ca.shared.global [%0], [%1], 8;"
                     :: "r"(d), "l"(g_meta + (size_t)(m0 + tid) * 64 + kk * 2));
    }
}

__global__ __launch_bounds__(256, 2) void gemm_sp_kernel() {
    extern __shared__ char smem[];
    uint32_t sbase = (uint32_t)__cvta_generic_to_shared(smem);

    int tid  = threadIdx.x;
    int lane = tid & 31;
    int wid  = tid >> 5;
    int wm = (wid >> 1) * 32;
    int wn = (wid & 1) * 64;
    int lr = lane >> 2;
    int lc = lane & 3;
    int m0 = blockIdx.y * BM;
    int n0 = blockIdx.x * BN;

    int a_row  = wm + (lane & 15);
    int a_csel = (lane >> 4) << 3;
    int b_row  = ((lane >> 4) << 3) + (lane & 7);
    int b_csel = ((lane >> 3) & 1) << 3;
    // metadata row provided by this lane (F=0: lane%4==0 -> rows 0-7, ==1 -> 8-15)
    int mrow = (((lane & 3) == 1) ? 8 : 0) + (lane >> 2);

    float acc[2][8][4];
#pragma unroll
    for (int mt = 0; mt < 2; mt++)
#pragma unroll
        for (int nt = 0; nt < 8; nt++)
#pragma unroll
            for (int q = 0; q < 4; q++) acc[mt][nt][q] = 0.0f;

    stage_load_sp(sbase, 0, 0, tid, m0, n0);
    asm volatile("cp.async.commit_group;" ::: "memory");
    stage_load_sp(sbase, 1, 1, tid, m0, n0);
    asm volatile("cp.async.commit_group;" ::: "memory");

#pragma unroll 1
    for (int kt = 0; kt < NKT; kt++) {
        asm volatile("cp.async.wait_group 1;" ::: "memory");
        __syncthreads();

        if (kt + 2 < NKT)
            stage_load_sp(sbase, (kt + 2) % 3, kt + 2, tid, m0, n0);
        asm volatile("cp.async.commit_group;" ::: "memory");

        if (kt == 32) {                      // plane boundary: acc = 2^-11 * C_res
#pragma unroll
            for (int mt = 0; mt < 2; mt++)
#pragma unroll
                for (int nt = 0; nt < 8; nt++)
#pragma unroll
                    for (int q = 0; q < 4; q++) acc[mt][nt][q] *= 4.8828125e-4f;
        }

        uint32_t stA = sbase + (uint32_t)(kt % 3) * SP_STAGE;
        uint32_t stB = stA + SP_A_BYTES;
        uint32_t stM = stB + SP_B_BYTES;
#pragma unroll
        for (int ks = 0; ks < 2; ks++) {
            uint32_t a[2][4];
            uint32_t e[2];
#pragma unroll
            for (int mt = 0; mt < 2; mt++) {
                ldsm_x4(a[mt], stA + (uint32_t)((a_row + mt * 16) * SP_ASTR + ks * 16 + a_csel) * 2);
                asm volatile("ld.shared.b32 %0, [%1];"
                             : "=r"(e[mt])
                             : "r"(stM + (uint32_t)((wm + mt * 16 + mrow) * 8 + ks * 4)));
            }
#pragma unroll
            for (int p = 0; p < 4; p++) {
                uint32_t lo[4], hi[4];
                ldsm_x4(lo, stB + (uint32_t)((wn + p * 16 + b_row) * SP_BSTR + ks * 32 + b_csel) * 2);
                ldsm_x4(hi, stB + (uint32_t)((wn + p * 16 + b_row) * SP_BSTR + ks * 32 + 16 + b_csel) * 2);
#pragma unroll
                for (int mt = 0; mt < 2; mt++) {
                    float* c0 = acc[mt][2 * p];
                    asm volatile(
                        "mma.sp::ordered_metadata.sync.aligned.m16n8k32.row.col.f32.f16.f16.f32 "
                        "{%0,%1,%2,%3}, {%4,%5,%6,%7}, {%8,%9,%10,%11}, {%0,%1,%2,%3}, %12, 0x0;"
                        : "+f"(c0[0]), "+f"(c0[1]), "+f"(c0[2]), "+f"(c0[3])
                        : "r"(a[mt][0]), "r"(a[mt][1]), "r"(a[mt][2]), "r"(a[mt][3]),
                          "r"(lo[0]), "r"(lo[1]), "r"(hi[0]), "r"(hi[1]), "r"(e[mt]));
                    float* c1 = acc[mt][2 * p + 1];
                    asm volatile(
                        "mma.sp::ordered_metadata.sync.aligned.m16n8k32.row.col.f32.f16.f16.f32 "
                        "{%0,%1,%2,%3}, {%4,%5,%6,%7}, {%8,%9,%10,%11}, {%0,%1,%2,%3}, %12, 0x0;"
                        : "+f"(c1[0]), "+f"(c1[1]), "+f"(c1[2]), "+f"(c1[3])
                        : "r"(a[mt][0]), "r"(a[mt][1]), "r"(a[mt][2]), "r"(a[mt][3]),
                          "r"(lo[2]), "r"(lo[3]), "r"(hi[2]), "r"(hi[3]), "r"(e[mt]));
                }
            }
        }
    }

    // ---- Fixup: add dropped spikes (2:4 overflow) exactly ----
    {
        int blk = blockIdx.y;
        int cnt = g_ovf_cnt[blk];
        if (cnt > OVF_CAP) cnt = OVF_CAP;
        for (int e2 = 0; e2 < cnt; e2++) {
            int ent = g_ovf[blk * OVF_CAP + e2];
            int ml = ent >> 16;
            int ig = ent & 0xFFFF;
            if (ml < wm || ml >= wm + 32) continue;
            int r16 = ml & 15;
            if ((lane >> 2) != (r16 & 7)) continue;
            int mt = (ml - wm) >> 4;
            int qh = (r16 >= 8) ? 2 : 0;
            const float* wf = g_wfix + (size_t)ig * Hdim + n0 + wn + lc * 2;
#pragma unroll
            for (int nt = 0; nt < 8; nt++) {
                float2 f = *reinterpret_cast<const float2*>(wf + nt * 8);
                acc[mt][nt][qh]     += f.x;
                acc[mt][nt][qh + 1] += f.y;
            }
        }
    }

    // ---- Epilogue: stage through smem as [t_local][h][b], write coalesced ----
    __syncthreads();
    float* epi = reinterpret_cast<float*>(smem);
#pragma unroll
    for (int mt = 0; mt < 2; mt++) {
#pragma unroll
        for (int q2 = 0; q2 < 2; q2++) {
            int row = wm + mt * 16 + lr + q2 * 8;
            int tl = row >> 6, bb = row & 63;
#pragma unroll
            for (int nt = 0; nt < 8; nt++) {
                int col = wn + nt * 8 + lc * 2;
                epi[((size_t)(tl * 128 + col)     * EPI_STR) + bb] = acc[mt][nt][q2 * 2 + 0];
                epi[((size_t)(tl * 128 + col + 1) * EPI_STR) + bb] = acc[mt][nt][q2 * 2 + 1];
            }
        }
    }
    __syncthreads();
    {
        int tl = tid >> 7;
        int h  = tid & 127;
        int t_glob = blockIdx.y * 2 + tl;
        float* dst = g_weightedT + ((size_t)t_glob * Hdim + n0 + h) * Bdim;
        const float* src = epi + (size_t)(tl * 128 + h) * EPI_STR;
#pragma unroll
        for (int j = 0; j < 64; j += 4) {
            float4 o;
            o.x = src[j]; o.y = src[j + 1]; o.z = src[j + 2]; o.w = src[j + 3];
            *reinterpret_cast<float4*>(dst + j) = o;
        }
    }
}

// ---------------------------------------------------------------------------
// Verify: 256 blocks, each recomputes one C entry densely from raw inputs.
// Mismatch -> g_fail = 1 -> dense fallback GEMM overwrites.
// ---------------------------------------------------------------------------
__global__ void verify_kernel(const float* __restrict__ spikes) {
    __shared__ float part[2];
    int bid = blockIdx.x, tid = threadIdx.x;   // 64 threads
    int m = (bid * 37 + 5) & (Mtot - 1);
    int h = (bid * 113 + 9) & (Hdim - 1);
    int t = m >> 6, b = m & 63;

    float r0 = 0.0f, r1 = 0.0f;
    for (int i = tid; i < Idim; i += 64) {
        float sp = spikes[((size_t)b * Idim + i) * Tdim + t];
        if (sp != 0.0f) {
            r0 += sp * __half2float(g_w0[(size_t)h * Idim + i]);
            r1 += sp * __half2float(g_w1[(size_t)h * Idim + i]);
        }
    }
    float v = r0 + 4.8828125e-4f * r1;
#pragma unroll
    for (int off = 16; off > 0; off >>= 1)
        v += __shfl_down_sync(0xffffffffu, v, off);
    if ((tid & 31) == 0) part[tid >> 5] = v;
    __syncthreads();
    if (tid == 0) {
        float ref = part[0] + part[1];
        float got = g_weightedT[((size_t)t * Hdim + h) * Bdim + b];
        if (fabsf(got - ref) > 1e-2f * (1.0f + fabsf(ref)))
            atomicExch(&g_fail, 1);
    }
}

// ---------------------------------------------------------------------------
// DENSE fallback GEMM (R10 verbatim + early-exit on g_fail==0).
// ---------------------------------------------------------------------------
#define ASTR 72
#define A_STG_H (BM * ASTR)
#define B_STG_H (BN * ASTR)
#define STAGE_BYTES ((A_STG_H + B_STG_H) * 2)
#define GEMM_SMEM (3 * STAGE_BYTES)

__device__ __forceinline__ void stage_load_d(uint32_t sbase, int stage, int kt,
                                             int tid, int m0, int n0) {
    const __half* Asrc = g_Ah + (size_t)m0 * Idim;
    const __half* Bsrc = (kt < 32 ? g_w1 : g_w0) + (size_t)n0 * Idim;
    int k0 = (kt & 31) * 64;
    uint32_t sA = sbase + (uint32_t)stage * STAGE_BYTES;
    uint32_t sB = sA + A_STG_H * 2;
#pragma unroll
    for (int i = 0; i < 4; i++) {
        int ch = tid + i * 256;
        int r = ch >> 3, c = ch & 7;
        uint32_t d = sA + (uint32_t)(r * ASTR + c * 8) * 2;
        asm volatile("cp.async.cg.shared.global [%0], [%1], 16;"
                     :: "r"(d), "l"(Asrc + (size_t)r * Idim + k0 + c * 8));
    }
#pragma unroll
    for (int i = 0; i < 4; i++) {
        int ch = tid + i * 256;
        int r = ch >> 3, c = ch & 7;
        uint32_t d = sB + (uint32_t)(r * ASTR + c * 8) * 2;
        asm volatile("cp.async.cg.shared.global [%0], [%1], 16;"
                     :: "r"(d), "l"(Bsrc + (size_t)r * Idim + k0 + c * 8));
    }
}

__global__ __launch_bounds__(256, 2) void gemm_dense_kernel() {
    if (g_fail == 0) return;
    extern __shared__ char smem[];
    uint32_t sbase = (uint32_t)__cvta_generic_to_shared(smem);

    int tid  = threadIdx.x;
    int lane = tid & 31;
    int wid  = tid >> 5;
    int wm = (wid >> 1) * 32;
    int wn = (wid & 1) * 64;
    int lr = lane >> 2;
    int lc = lane & 3;
    int m0 = blockIdx.y * BM;
    int n0 = blockIdx.x * BN;

    int a_row  = wm + (lane & 15);
    int a_csel = (lane >> 4) << 3;
    int b_row  = ((lane >> 4) << 3) + (lane & 7);
    int b_csel = ((lane >> 3) & 1) << 3;

    float acc[2][8][4];
#pragma unroll
    for (int mt = 0; mt < 2; mt++)
#pragma unroll
        for (int nt = 0; nt < 8; nt++)
#pragma unroll
            for (int q = 0; q < 4; q++) acc[mt][nt][q] = 0.0f;

    stage_load_d(sbase, 0, 0, tid, m0, n0);
    asm volatile("cp.async.commit_group;" ::: "memory");
    stage_load_d(sbase, 1, 1, tid, m0, n0);
    asm volatile("cp.async.commit_group;" ::: "memory");

#pragma unroll 1
    for (int kt = 0; kt < NKT; kt++) {
        asm volatile("cp.async.wait_group 1;" ::: "memory");
        __syncthreads();
        if (kt + 2 < NKT)
            stage_load_d(sbase, (kt + 2) % 3, kt + 2, tid, m0, n0);
        asm volatile("cp.async.commit_group;" ::: "memory");

        if (kt == 32) {
#pragma unroll
            for (int mt = 0; mt < 2; mt++)
#pragma unroll
                for (int nt = 0; nt < 8; nt++)
#pragma unroll
                    for (int q = 0; q < 4; q++) acc[mt][nt][q] *= 4.8828125e-4f;
        }

        uint32_t stA = sbase + (uint32_t)(kt % 3) * STAGE_BYTES;
        uint32_t stB = stA + A_STG_H * 2;
#pragma unroll
        for (int ks = 0; ks < 4; ks++) {
            int kb = ks * 16;
            uint32_t a[2][4];
#pragma unroll
            for (int mt = 0; mt < 2; mt++)
                ldsm_x4(a[mt], stA + (uint32_t)((a_row + mt * 16) * ASTR + kb + a_csel) * 2);
            uint32_t bf[8][2];
#pragma unroll
            for (int p = 0; p < 4; p++) {
                uint32_t r[4];
                ldsm_x4(r, stB + (uint32_t)((wn + p * 16 + b_row) * ASTR + kb + b_csel) * 2);
                bf[2 * p][0] = r[0]; bf[2 * p][1] = r[1];
                bf[2 * p + 1][0] = r[2]; bf[2 * p + 1][1] = r[3];
            }
#pragma unroll
            for (int nt = 0; nt < 8; nt++)
#pragma unroll
                for (int mt = 0; mt < 2; mt++) {
                    float* c = acc[mt][nt];
                    asm volatile(
                        "mma.sync.aligned.m16n8k16.row.col.f32.f16.f16.f32 "
                        "{%0,%1,%2,%3}, {%4,%5,%6,%7}, {%8,%9}, {%0,%1,%2,%3};"
                        : "+f"(c[0]), "+f"(c[1]), "+f"(c[2]), "+f"(c[3])
                        : "r"(a[mt][0]), "r"(a[mt][1]), "r"(a[mt][2]), "r"(a[mt][3]),
                          "r"(bf[nt][0]), "r"(bf[nt][1]));
                }
        }
    }

    __syncthreads();
    float* epi = reinterpret_cast<float*>(smem);
#pragma unroll
    for (int mt = 0; mt < 2; mt++) {
#pragma unroll
        for (int q2 = 0; q2 < 2; q2++) {
            int row = wm + mt * 16 + lr + q2 * 8;
            int tl = row >> 6, bb = row & 63;
#pragma unroll
            for (int nt = 0; nt < 8; nt++) {
                int col = wn + nt * 8 + lc * 2;
                epi[((size_t)(tl * 128 + col)     * EPI_STR) + bb] = acc[mt][nt][q2 * 2 + 0];
                epi[((size_t)(tl * 128 + col + 1) * EPI_STR) + bb] = acc[mt][nt][q2 * 2 + 1];
            }
        }
    }
    __syncthreads();
    {
        int tl = tid >> 7;
        int h  = tid & 127;
        int t_glob = blockIdx.y * 2 + tl;
        float* dst = g_weightedT + ((size_t)t_glob * Hdim + n0 + h) * Bdim;
        const float* src = epi + (size_t)(tl * 128 + h) * EPI_STR;
#pragma unroll
        for (int j = 0; j < 64; j += 4) {
            float4 o;
            o.x = src[j]; o.y = src[j + 1]; o.z = src[j + 2]; o.w = src[j + 3];
            *reinterpret_cast<float4*>(dst + j) = o;
        }
    }
}

// ---------------------------------------------------------------------------
// LIF scan: one warp per h, lanes own b = 2*lane, 2*lane+1. (R8 verbatim)
// ---------------------------------------------------------------------------
__global__ __launch_bounds__(256) void scan_kernel(
    const float* __restrict__ threshold,
    const float* __restrict__ p_tau_mem, const float* __restrict__ p_tau_syn,
    const float* __restrict__ p_target,  const float* __restrict__ p_lr,
    float* __restrict__ out)
{
    int tid  = threadIdx.x;
    int lane = tid & 31;
    int h    = blockIdx.x * 8 + (tid >> 5);

    float tau_m = *p_tau_mem, tau_s = *p_tau_syn;
    float a_mem = (float)exp(-(double)(0.001f / tau_m));
    float a_syn = (float)exp(-(double)(0.001f / tau_s));
    float target = *p_target, lr = *p_lr;

    float thr = threshold[h];
    float fre = 0.0f;
    float isyn0 = 0.0f, v0 = 0.0f, isyn1 = 0.0f, v1 = 0.0f;
    unsigned sb0[4] = {0u, 0u, 0u, 0u};
    unsigned sb1[4] = {0u, 0u, 0u, 0u};

    const float* wptr = g_weightedT + (size_t)h * Bdim + lane * 2;
    const size_t TSTR = (size_t)Hdim * Bdim;

    float2 wbuf[4];
#pragma unroll
    for (int p = 0; p < 4; p++)
        wbuf[p] = *reinterpret_cast<const float2*>(wptr + p * TSTR);

#pragma unroll 4
    for (int t = 0; t < Tdim; ++t) {
        float2 w = wbuf[0];
        wbuf[0] = wbuf[1]; wbuf[1] = wbuf[2]; wbuf[2] = wbuf[3];
        if (t + 4 < Tdim)
            wbuf[3] = *reinterpret_cast<const float2*>(wptr + (size_t)(t + 4) * TSTR);

        isyn0 = fmaf(a_syn, isyn0, w.x);
        v0    = fmaf(a_mem, v0, isyn0);
        isyn1 = fmaf(a_syn, isyn1, w.y);
        v1    = fmaf(a_mem, v1, isyn1);
        bool p0 = (v0 >= thr), p1 = (v1 >= thr);
        if (p0) { v0 -= thr; sb0[t >> 5] |= (1u << (t & 31)); }
        if (p1) { v1 -= thr; sb1[t >> 5] |= (1u << (t & 31)); }

        unsigned m0 = __ballot_sync(0xffffffffu, p0);
        unsigned m1 = __ballot_sync(0xffffffffu, p1);
        float s = (float)(__popc(m0) + __popc(m1));

        float rate = s * (1.0f / 64.0f);
        fre = 0.99f * fre + 0.01f * rate;
        thr = thr + lr * (fre - target);
    }

    int bsel = (lane & 7) * 4;
#pragma unroll 4
    for (int bb = 0; bb < 64; ++bb) {
        int src = bb >> 1;
        unsigned w0, w1, w2, w3;
        if (bb & 1) {
            w0 = __shfl_sync(0xffffffffu, sb1[0], src);
            w1 = __shfl_sync(0xffffffffu, sb1[1], src);
            w2 = __shfl_sync(0xffffffffu, sb1[2], src);
            w3 = __shfl_sync(0xffffffffu, sb1[3], src);
        } else {
            w0 = __shfl_sync(0xffffffffu, sb0[0], src);
            w1 = __shfl_sync(0xffffffffu, sb0[1], src);
            w2 = __shfl_sync(0xffffffffu, sb0[2], src);
            w3 = __shfl_sync(0xffffffffu, sb0[3], src);
        }
        unsigned wsel = (lane < 8) ? w0 : (lane < 16) ? w1 : (lane < 24) ? w2 : w3;
        unsigned bits = (wsel >> bsel) & 0xFu;
        float4 o;
        o.x = (float)(bits & 1u);
        o.y = (float)((bits >> 1) & 1u);
        o.z = (float)((bits >> 2) & 1u);
        o.w = (float)((bits >> 3) & 1u);
        *reinterpret_cast<float4*>(
            out + ((size_t)bb * Hdim + h) * Tdim + lane * 4) = o;
    }
}

// ---------------------------------------------------------------------------
extern "C" void kernel_launch(void* const* d_in, const int* in_sizes, int n_in,
                              void* d_out, int out_size) {
    const float* spikes    = (const float*)d_in[0];
    const float* weight    = (const float*)d_in[1];
    const float* strength  = (const float*)d_in[2];
    const float* threshold = (const float*)d_in[3];
    const float* tau_mem   = (const float*)d_in[4];
    const float* tau_syn   = (const float*)d_in[5];
    const float* target    = (const float*)d_in[6];
    const float* lr        = (const float*)d_in[7];
    float* out = (float*)d_out;

    cudaFuncSetAttribute(gemm_sp_kernel,
                         cudaFuncAttributeMaxDynamicSharedMemorySize, SP_SMEM);
    cudaFuncSetAttribute(gemm_dense_kernel,
                         cudaFuncAttributeMaxDynamicSharedMemorySize, GEMM_SMEM);

    reset_kernel<<<1, 128>>>();
    prep_kernel<<<20480, dim3(32, 8)>>>(spikes, weight, strength);
    gemm_sp_kernel<<<dim3(Hdim / BN, Mtot / BM), 256, SP_SMEM>>>();
    verify_kernel<<<256, 64>>>(spikes);
    gemm_dense_kernel<<<dim3(Hdim / BN, Mtot / BM), 256, GEMM_SMEM>>>();
    scan_kernel<<<Hdim / 8, 256>>>(threshold, tau_mem, tau_syn, target, lr, out);
}

// round 12
// speedup vs baseline: 3.9076x; 3.9076x over previous
#include <cuda_runtime.h>
#include <cuda_fp16.h>
#include <cstdint>
#include <math.h>

#define Bdim 64
#define Idim 2048
#define Hdim 2048
#define Tdim 128
#define Mtot (Tdim * Bdim)          // 8192 rows (t,b)

// ---------------- scratch (device globals; allocation-free) ----------------
__device__ __half g_Ah[(size_t)Mtot * Idim];          // 32 MB  [t*B+b][i]
__device__ __half g_w0[(size_t)Hdim * Idim];          // 8 MB   hi plane [h][i]
__device__ __half g_w1[(size_t)Hdim * Idim];          // 8 MB   res*2^11 [h][i]
__device__ float  g_weightedT[(size_t)Tdim * Hdim * Bdim];  // 64 MB [t][h][b]

// ---------------------------------------------------------------------------
// Fused prep, 128B loads AND stores.
// blocks [0,8192): spikes [B][I][T] -> g_Ah [(t*B+b)][i], tiles 64i x 32t
// blocks [8192,10240): w_eff split -> g_w0/g_w1 [h][i],  tiles 64i x 32h
// ---------------------------------------------------------------------------
__global__ __launch_bounds__(256) void prep_kernel(const float* __restrict__ in,
                                                   const float* __restrict__ w,
                                                   const float* __restrict__ s) {
    __shared__ float tile[64][33];
    int bid = blockIdx.x;
    int tx = threadIdx.x, ty = threadIdx.y;
    int tid = ty * 32 + tx;
    int orow = tid >> 3;              // 0..31 output row
    int ic0  = (tid & 7) * 8;         // 0..56 i-column base

    if (bid < 8192) {
        // spikes: t0 in {0,32,64,96}, i0 64-wide, b
        int t0 = (bid & 3) * 32;
        int i0 = ((bid >> 2) & 31) * 64;
        int b  = bid >> 7;
#pragma unroll
        for (int j = 0; j < 8; j++)
            tile[ty + j * 8][tx] = in[((size_t)b * Idim + i0 + ty + j * 8) * Tdim + t0 + tx];
        __syncthreads();
        __half h[8];
#pragma unroll
        for (int q = 0; q < 8; q++)
            h[q] = __float2half_rn(tile[ic0 + q][orow]);
        *reinterpret_cast<uint4*>(
            g_Ah + ((size_t)(t0 + orow) * Bdim + b) * Idim + i0 + ic0)
            = *reinterpret_cast<uint4*>(h);
    } else {
        // weights: i0 64-wide, h0 32-wide
        int sid = bid - 8192;
        int i0 = (sid & 31) * 64;
        int h0 = (sid >> 5) * 32;
#pragma unroll
        for (int j = 0; j < 8; j++) {
            size_t idx = (size_t)(i0 + ty + j * 8) * Hdim + h0 + tx;
            tile[ty + j * 8][tx] = w[idx] * s[idx];
        }
        __syncthreads();
        __half hh[8], hl[8];
#pragma unroll
        for (int q = 0; q < 8; q++) {
            float v = tile[ic0 + q][orow];
            __half hi = __float2half_rn(v);
            float r = v - __half2float(hi);             // exact (Fast2Sum)
            hh[q] = hi;
            hl[q] = __float2half_rn(r * 2048.0f);
        }
        size_t o = (size_t)(h0 + orow) * Idim + i0 + ic0;
        *reinterpret_cast<uint4*>(g_w0 + o) = *reinterpret_cast<uint4*>(hh);
        *reinterpret_cast<uint4*>(g_w1 + o) = *reinterpret_cast<uint4*>(hl);
    }
}

// ---------------------------------------------------------------------------
// mma.sync GEMM: C = A @ W0^T + 2^-11 * (A @ W1^T), fp32 acc (R10 verbatim).
// CTA 128x128, BK=64, 256 threads (8 warps, warp tile 32x64), 3-stage
// cp.async pipeline, ldmatrix.x4, fused 64-kt loop, 2 CTAs/SM.
// ---------------------------------------------------------------------------
#define BM 128
#define BN 128
#define BK 64
#define ASTR 72                          // halves per smem row (144 B)
#define A_STG_H (BM * ASTR)
#define B_STG_H (BN * ASTR)
#define STAGE_BYTES ((A_STG_H + B_STG_H) * 2)   // 36864 B
#define GEMM_SMEM (3 * STAGE_BYTES)             // 110592 B
#define NKT 64
#define EPI_STR 65

__device__ __forceinline__ void ldsm_x4(uint32_t* r, uint32_t addr) {
    asm volatile("ldmatrix.sync.aligned.m8n8.x4.shared.b16 {%0,%1,%2,%3}, [%4];"
                 : "=r"(r[0]), "=r"(r[1]), "=r"(r[2]), "=r"(r[3]) : "r"(addr));
}

__device__ __forceinline__ void stage_load(uint32_t sbase, int stage, int kt,
                                           int tid, int m0, int n0) {
    const __half* Asrc = g_Ah + (size_t)m0 * Idim;
    const __half* Bsrc = (kt < 32 ? g_w1 : g_w0) + (size_t)n0 * Idim;
    int k0 = (kt & 31) * BK;
    uint32_t sA = sbase + (uint32_t)stage * STAGE_BYTES;
    uint32_t sB = sA + A_STG_H * 2;
#pragma unroll
    for (int i = 0; i < 4; i++) {               // A: 128 rows x 8 chunks16B
        int ch = tid + i * 256;
        int r = ch >> 3, c = ch & 7;
        uint32_t d = sA + (uint32_t)(r * ASTR + c * 8) * 2;
        asm volatile("cp.async.cg.shared.global [%0], [%1], 16;"
                     :: "r"(d), "l"(Asrc + (size_t)r * Idim + k0 + c * 8));
    }
#pragma unroll
    for (int i = 0; i < 4; i++) {               // B: 128 rows x 8 chunks16B
        int ch = tid + i * 256;
        int r = ch >> 3, c = ch & 7;
        uint32_t d = sB + (uint32_t)(r * ASTR + c * 8) * 2;
        asm volatile("cp.async.cg.shared.global [%0], [%1], 16;"
                     :: "r"(d), "l"(Bsrc + (size_t)r * Idim + k0 + c * 8));
    }
}

__global__ __launch_bounds__(256, 2) void gemm_mma_kernel() {
    extern __shared__ char smem[];
    uint32_t sbase = (uint32_t)__cvta_generic_to_shared(smem);

    int tid  = threadIdx.x;
    int lane = tid & 31;
    int wid  = tid >> 5;
    int wm = (wid >> 1) * 32;            // 0,32,64,96
    int wn = (wid & 1) * 64;             // 0,64
    int lr = lane >> 2;
    int lc = lane & 3;
    int m0 = blockIdx.y * BM;
    int n0 = blockIdx.x * BN;

    int a_row  = wm + (lane & 15);
    int a_csel = (lane >> 4) << 3;
    int b_row  = ((lane >> 4) << 3) + (lane & 7);
    int b_csel = ((lane >> 3) & 1) << 3;

    float acc[2][8][4];
#pragma unroll
    for (int mt = 0; mt < 2; mt++)
#pragma unroll
        for (int nt = 0; nt < 8; nt++)
#pragma unroll
            for (int q = 0; q < 4; q++) acc[mt][nt][q] = 0.0f;

    stage_load(sbase, 0, 0, tid, m0, n0);
    asm volatile("cp.async.commit_group;" ::: "memory");
    stage_load(sbase, 1, 1, tid, m0, n0);
    asm volatile("cp.async.commit_group;" ::: "memory");

#pragma unroll 1
    for (int kt = 0; kt < NKT; kt++) {
        asm volatile("cp.async.wait_group 1;" ::: "memory");
        __syncthreads();

        if (kt + 2 < NKT)
            stage_load(sbase, (kt + 2) % 3, kt + 2, tid, m0, n0);
        asm volatile("cp.async.commit_group;" ::: "memory");

        if (kt == 32) {                  // pass boundary: acc = 2^-11 * C_res
#pragma unroll
            for (int mt = 0; mt < 2; mt++)
#pragma unroll
                for (int nt = 0; nt < 8; nt++)
#pragma unroll
                    for (int q = 0; q < 4; q++) acc[mt][nt][q] *= 4.8828125e-4f;
        }

        uint32_t stA = sbase + (uint32_t)(kt % 3) * STAGE_BYTES;
        uint32_t stB = stA + A_STG_H * 2;
#pragma unroll
        for (int ks = 0; ks < 4; ks++) {
            int kb = ks * 16;
            uint32_t a[2][4];
#pragma unroll
            for (int mt = 0; mt < 2; mt++)
                ldsm_x4(a[mt], stA + (uint32_t)((a_row + mt * 16) * ASTR + kb + a_csel) * 2);
            uint32_t bf[8][2];
#pragma unroll
            for (int p = 0; p < 4; p++) {
                uint32_t r[4];
                ldsm_x4(r, stB + (uint32_t)((wn + p * 16 + b_row) * ASTR + kb + b_csel) * 2);
                bf[2 * p][0] = r[0]; bf[2 * p][1] = r[1];
                bf[2 * p + 1][0] = r[2]; bf[2 * p + 1][1] = r[3];
            }
#pragma unroll
            for (int nt = 0; nt < 8; nt++)
#pragma unroll
                for (int mt = 0; mt < 2; mt++) {
                    float* c = acc[mt][nt];
                    asm volatile(
                        "mma.sync.aligned.m16n8k16.row.col.f32.f16.f16.f32 "
                        "{%0,%1,%2,%3}, {%4,%5,%6,%7}, {%8,%9}, {%0,%1,%2,%3};"
                        : "+f"(c[0]), "+f"(c[1]), "+f"(c[2]), "+f"(c[3])
                        : "r"(a[mt][0]), "r"(a[mt][1]), "r"(a[mt][2]), "r"(a[mt][3]),
                          "r"(bf[nt][0]), "r"(bf[nt][1]));
                }
        }
    }

    // ---- Epilogue: stage through smem as [t_local][h][b], write coalesced ----
    __syncthreads();
    float* epi = reinterpret_cast<float*>(smem);   // [2][128][EPI_STR]
#pragma unroll
    for (int mt = 0; mt < 2; mt++) {
#pragma unroll
        for (int q2 = 0; q2 < 2; q2++) {
            int row = wm + mt * 16 + lr + q2 * 8;   // local row 0..127
            int tl = row >> 6, bb = row & 63;
#pragma unroll
            for (int nt = 0; nt < 8; nt++) {
                int col = wn + nt * 8 + lc * 2;
                epi[((size_t)(tl * 128 + col)     * EPI_STR) + bb] = acc[mt][nt][q2 * 2 + 0];
                epi[((size_t)(tl * 128 + col + 1) * EPI_STR) + bb] = acc[mt][nt][q2 * 2 + 1];
            }
        }
    }
    __syncthreads();
    {
        int tl = tid >> 7;                 // 0..1
        int h  = tid & 127;                // 0..127
        int t_glob = blockIdx.y * 2 + tl;
        float* dst = g_weightedT + ((size_t)t_glob * Hdim + n0 + h) * Bdim;
        const float* src = epi + (size_t)(tl * 128 + h) * EPI_STR;
#pragma unroll
        for (int j = 0; j < 64; j += 4) {
            float4 o;
            o.x = src[j]; o.y = src[j + 1]; o.z = src[j + 2]; o.w = src[j + 3];
            *reinterpret_cast<float4*>(dst + j) = o;
        }
    }
}

// ---------------------------------------------------------------------------
// LIF scan: one warp per h, lanes own b = 2*lane, 2*lane+1. (R10 verbatim)
// ---------------------------------------------------------------------------
__global__ __launch_bounds__(256) void scan_kernel(
    const float* __restrict__ threshold,
    const float* __restrict__ p_tau_mem, const float* __restrict__ p_tau_syn,
    const float* __restrict__ p_target,  const float* __restrict__ p_lr,
    float* __restrict__ out)
{
    int tid  = threadIdx.x;
    int lane = tid & 31;
    int h    = blockIdx.x * 8 + (tid >> 5);

    float tau_m = *p_tau_mem, tau_s = *p_tau_syn;
    float a_mem = (float)exp(-(double)(0.001f / tau_m));
    float a_syn = (float)exp(-(double)(0.001f / tau_s));
    float target = *p_target, lr = *p_lr;

    float thr = threshold[h];
    float fre = 0.0f;
    float isyn0 = 0.0f, v0 = 0.0f, isyn1 = 0.0f, v1 = 0.0f;
    unsigned sb0[4] = {0u, 0u, 0u, 0u};
    unsigned sb1[4] = {0u, 0u, 0u, 0u};

    const float* wptr = g_weightedT + (size_t)h * Bdim + lane * 2;
    const size_t TSTR = (size_t)Hdim * Bdim;

    float2 wbuf[4];
#pragma unroll
    for (int p = 0; p < 4; p++)
        wbuf[p] = *reinterpret_cast<const float2*>(wptr + p * TSTR);

#pragma unroll 4
    for (int t = 0; t < Tdim; ++t) {
        float2 w = wbuf[0];
        wbuf[0] = wbuf[1]; wbuf[1] = wbuf[2]; wbuf[2] = wbuf[3];
        if (t + 4 < Tdim)
            wbuf[3] = *reinterpret_cast<const float2*>(wptr + (size_t)(t + 4) * TSTR);

        isyn0 = fmaf(a_syn, isyn0, w.x);
        v0    = fmaf(a_mem, v0, isyn0);
        isyn1 = fmaf(a_syn, isyn1, w.y);
        v1    = fmaf(a_mem, v1, isyn1);
        bool p0 = (v0 >= thr), p1 = (v1 >= thr);
        if (p0) { v0 -= thr; sb0[t >> 5] |= (1u << (t & 31)); }
        if (p1) { v1 -= thr; sb1[t >> 5] |= (1u << (t & 31)); }

        unsigned m0 = __ballot_sync(0xffffffffu, p0);
        unsigned m1 = __ballot_sync(0xffffffffu, p1);
        float s = (float)(__popc(m0) + __popc(m1));      // exact int

        float rate = s * (1.0f / 64.0f);
        fre = 0.99f * fre + 0.01f * rate;
        thr = thr + lr * (fre - target);
    }

    int bsel = (lane & 7) * 4;
#pragma unroll 4
    for (int bb = 0; bb < 64; ++bb) {
        int src = bb >> 1;
        unsigned w0, w1, w2, w3;
        if (bb & 1) {
            w0 = __shfl_sync(0xffffffffu, sb1[0], src);
            w1 = __shfl_sync(0xffffffffu, sb1[1], src);
            w2 = __shfl_sync(0xffffffffu, sb1[2], src);
            w3 = __shfl_sync(0xffffffffu, sb1[3], src);
        } else {
            w0 = __shfl_sync(0xffffffffu, sb0[0], src);
            w1 = __shfl_sync(0xffffffffu, sb0[1], src);
            w2 = __shfl_sync(0xffffffffu, sb0[2], src);
            w3 = __shfl_sync(0xffffffffu, sb0[3], src);
        }
        unsigned wsel = (lane < 8) ? w0 : (lane < 16) ? w1 : (lane < 24) ? w2 : w3;
        unsigned bits = (wsel >> bsel) & 0xFu;
        float4 o;
        o.x = (float)(bits & 1u);
        o.y = (float)((bits >> 1) & 1u);
        o.z = (float)((bits >> 2) & 1u);
        o.w = (float)((bits >> 3) & 1u);
        *reinterpret_cast<float4*>(
            out + ((size_t)bb * Hdim + h) * Tdim + lane * 4) = o;
    }
}

// ---------------------------------------------------------------------------
extern "C" void kernel_launch(void* const* d_in, const int* in_sizes, int n_in,
                              void* d_out, int out_size) {
    const float* spikes    = (const float*)d_in[0];
    const float* weight    = (const float*)d_in[1];
    const float* strength  = (const float*)d_in[2];
    const float* threshold = (const float*)d_in[3];
    const float* tau_mem   = (const float*)d_in[4];
    const float* tau_syn   = (const float*)d_in[5];
    const float* target    = (const float*)d_in[6];
    const float* lr        = (const float*)d_in[7];
    float* out = (float*)d_out;

    cudaFuncSetAttribute(gemm_mma_kernel,
                         cudaFuncAttributeMaxDynamicSharedMemorySize, GEMM_SMEM);

    prep_kernel<<<10240, dim3(32, 8)>>>(spikes, weight, strength);
    gemm_mma_kernel<<<dim3(Hdim / BN, Mtot / BM), 256, GEMM_SMEM>>>();
    scan_kernel<<<Hdim / 8, 256>>>(threshold, tau_mem, tau_syn, target, lr, out);
}

// round 13
// speedup vs baseline: 4.0739x; 1.0426x over previous
#include <cuda_runtime.h>
#include <cuda_fp16.h>
#include <cstdint>
#include <math.h>

#define Bdim 64
#define Idim 2048
#define Hdim 2048
#define Tdim 128
#define Mtot (Tdim * Bdim)          // 8192 rows (t,b)

// ---------------- scratch (device globals; allocation-free) ----------------
__device__ __half g_Ah[(size_t)Mtot * Idim];          // 32 MB  [t*B+b][i]
__device__ __half g_w0[(size_t)Hdim * Idim];          // 8 MB   hi plane [h][i]
__device__ __half g_w1[(size_t)Hdim * Idim];          // 8 MB   res*2^11 [h][i]
__device__ float  g_weightedT[(size_t)Tdim * Hdim * Bdim];  // 64 MB [t][h][b]

// ---------------------------------------------------------------------------
// Fused prep, 128B loads AND stores. (R12 verbatim)
// ---------------------------------------------------------------------------
__global__ __launch_bounds__(256) void prep_kernel(const float* __restrict__ in,
                                                   const float* __restrict__ w,
                                                   const float* __restrict__ s) {
    __shared__ float tile[64][33];
    int bid = blockIdx.x;
    int tx = threadIdx.x, ty = threadIdx.y;
    int tid = ty * 32 + tx;
    int orow = tid >> 3;              // 0..31 output row
    int ic0  = (tid & 7) * 8;         // 0..56 i-column base

    if (bid < 8192) {
        int t0 = (bid & 3) * 32;
        int i0 = ((bid >> 2) & 31) * 64;
        int b  = bid >> 7;
#pragma unroll
        for (int j = 0; j < 8; j++)
            tile[ty + j * 8][tx] = in[((size_t)b * Idim + i0 + ty + j * 8) * Tdim + t0 + tx];
        __syncthreads();
        __half h[8];
#pragma unroll
        for (int q = 0; q < 8; q++)
            h[q] = __float2half_rn(tile[ic0 + q][orow]);
        *reinterpret_cast<uint4*>(
            g_Ah + ((size_t)(t0 + orow) * Bdim + b) * Idim + i0 + ic0)
            = *reinterpret_cast<uint4*>(h);
    } else {
        int sid = bid - 8192;
        int i0 = (sid & 31) * 64;
        int h0 = (sid >> 5) * 32;
#pragma unroll
        for (int j = 0; j < 8; j++) {
            size_t idx = (size_t)(i0 + ty + j * 8) * Hdim + h0 + tx;
            tile[ty + j * 8][tx] = w[idx] * s[idx];
        }
        __syncthreads();
        __half hh[8], hl[8];
#pragma unroll
        for (int q = 0; q < 8; q++) {
            float v = tile[ic0 + q][orow];
            __half hi = __float2half_rn(v);
            float r = v - __half2float(hi);             // exact (Fast2Sum)
            hh[q] = hi;
            hl[q] = __float2half_rn(r * 2048.0f);
        }
        size_t o = (size_t)(h0 + orow) * Idim + i0 + ic0;
        *reinterpret_cast<uint4*>(g_w0 + o) = *reinterpret_cast<uint4*>(hh);
        *reinterpret_cast<uint4*>(g_w1 + o) = *reinterpret_cast<uint4*>(hl);
    }
}

// ---------------------------------------------------------------------------
// mma.sync GEMM (R10/R12 verbatim; at the HMMA issue ceiling).
// ---------------------------------------------------------------------------
#define BM 128
#define BN 128
#define BK 64
#define ASTR 72                          // halves per smem row (144 B)
#define A_STG_H (BM * ASTR)
#define B_STG_H (BN * ASTR)
#define STAGE_BYTES ((A_STG_H + B_STG_H) * 2)   // 36864 B
#define GEMM_SMEM (3 * STAGE_BYTES)             // 110592 B
#define NKT 64
#define EPI_STR 65

__device__ __forceinline__ void ldsm_x4(uint32_t* r, uint32_t addr) {
    asm volatile("ldmatrix.sync.aligned.m8n8.x4.shared.b16 {%0,%1,%2,%3}, [%4];"
                 : "=r"(r[0]), "=r"(r[1]), "=r"(r[2]), "=r"(r[3]) : "r"(addr));
}

__device__ __forceinline__ void stage_load(uint32_t sbase, int stage, int kt,
                                           int tid, int m0, int n0) {
    const __half* Asrc = g_Ah + (size_t)m0 * Idim;
    const __half* Bsrc = (kt < 32 ? g_w1 : g_w0) + (size_t)n0 * Idim;
    int k0 = (kt & 31) * BK;
    uint32_t sA = sbase + (uint32_t)stage * STAGE_BYTES;
    uint32_t sB = sA + A_STG_H * 2;
#pragma unroll
    for (int i = 0; i < 4; i++) {
        int ch = tid + i * 256;
        int r = ch >> 3, c = ch & 7;
        uint32_t d = sA + (uint32_t)(r * ASTR + c * 8) * 2;
        asm volatile("cp.async.cg.shared.global [%0], [%1], 16;"
                     :: "r"(d), "l"(Asrc + (size_t)r * Idim + k0 + c * 8));
    }
#pragma unroll
    for (int i = 0; i < 4; i++) {
        int ch = tid + i * 256;
        int r = ch >> 3, c = ch & 7;
        uint32_t d = sB + (uint32_t)(r * ASTR + c * 8) * 2;
        asm volatile("cp.async.cg.shared.global [%0], [%1], 16;"
                     :: "r"(d), "l"(Bsrc + (size_t)r * Idim + k0 + c * 8));
    }
}

__global__ __launch_bounds__(256, 2) void gemm_mma_kernel() {
    extern __shared__ char smem[];
    uint32_t sbase = (uint32_t)__cvta_generic_to_shared(smem);

    int tid  = threadIdx.x;
    int lane = tid & 31;
    int wid  = tid >> 5;
    int wm = (wid >> 1) * 32;
    int wn = (wid & 1) * 64;
    int lr = lane >> 2;
    int lc = lane & 3;
    int m0 = blockIdx.y * BM;
    int n0 = blockIdx.x * BN;

    int a_row  = wm + (lane & 15);
    int a_csel = (lane >> 4) << 3;
    int b_row  = ((lane >> 4) << 3) + (lane & 7);
    int b_csel = ((lane >> 3) & 1) << 3;

    float acc[2][8][4];
#pragma unroll
    for (int mt = 0; mt < 2; mt++)
#pragma unroll
        for (int nt = 0; nt < 8; nt++)
#pragma unroll
            for (int q = 0; q < 4; q++) acc[mt][nt][q] = 0.0f;

    stage_load(sbase, 0, 0, tid, m0, n0);
    asm volatile("cp.async.commit_group;" ::: "memory");
    stage_load(sbase, 1, 1, tid, m0, n0);
    asm volatile("cp.async.commit_group;" ::: "memory");

#pragma unroll 1
    for (int kt = 0; kt < NKT; kt++) {
        asm volatile("cp.async.wait_group 1;" ::: "memory");
        __syncthreads();

        if (kt + 2 < NKT)
            stage_load(sbase, (kt + 2) % 3, kt + 2, tid, m0, n0);
        asm volatile("cp.async.commit_group;" ::: "memory");

        if (kt == 32) {                  // pass boundary: acc = 2^-11 * C_res
#pragma unroll
            for (int mt = 0; mt < 2; mt++)
#pragma unroll
                for (int nt = 0; nt < 8; nt++)
#pragma unroll
                    for (int q = 0; q < 4; q++) acc[mt][nt][q] *= 4.8828125e-4f;
        }

        uint32_t stA = sbase + (uint32_t)(kt % 3) * STAGE_BYTES;
        uint32_t stB = stA + A_STG_H * 2;
#pragma unroll
        for (int ks = 0; ks < 4; ks++) {
            int kb = ks * 16;
            uint32_t a[2][4];
#pragma unroll
            for (int mt = 0; mt < 2; mt++)
                ldsm_x4(a[mt], stA + (uint32_t)((a_row + mt * 16) * ASTR + kb + a_csel) * 2);
            uint32_t bf[8][2];
#pragma unroll
            for (int p = 0; p < 4; p++) {
                uint32_t r[4];
                ldsm_x4(r, stB + (uint32_t)((wn + p * 16 + b_row) * ASTR + kb + b_csel) * 2);
                bf[2 * p][0] = r[0]; bf[2 * p][1] = r[1];
                bf[2 * p + 1][0] = r[2]; bf[2 * p + 1][1] = r[3];
            }
#pragma unroll
            for (int nt = 0; nt < 8; nt++)
#pragma unroll
                for (int mt = 0; mt < 2; mt++) {
                    float* c = acc[mt][nt];
                    asm volatile(
                        "mma.sync.aligned.m16n8k16.row.col.f32.f16.f16.f32 "
                        "{%0,%1,%2,%3}, {%4,%5,%6,%7}, {%8,%9}, {%0,%1,%2,%3};"
                        : "+f"(c[0]), "+f"(c[1]), "+f"(c[2]), "+f"(c[3])
                        : "r"(a[mt][0]), "r"(a[mt][1]), "r"(a[mt][2]), "r"(a[mt][3]),
                          "r"(bf[nt][0]), "r"(bf[nt][1]));
                }
        }
    }

    __syncthreads();
    float* epi = reinterpret_cast<float*>(smem);
#pragma unroll
    for (int mt = 0; mt < 2; mt++) {
#pragma unroll
        for (int q2 = 0; q2 < 2; q2++) {
            int row = wm + mt * 16 + lr + q2 * 8;
            int tl = row >> 6, bb = row & 63;
#pragma unroll
            for (int nt = 0; nt < 8; nt++) {
                int col = wn + nt * 8 + lc * 2;
                epi[((size_t)(tl * 128 + col)     * EPI_STR) + bb] = acc[mt][nt][q2 * 2 + 0];
                epi[((size_t)(tl * 128 + col + 1) * EPI_STR) + bb] = acc[mt][nt][q2 * 2 + 1];
            }
        }
    }
    __syncthreads();
    {
        int tl = tid >> 7;
        int h  = tid & 127;
        int t_glob = blockIdx.y * 2 + tl;
        float* dst = g_weightedT + ((size_t)t_glob * Hdim + n0 + h) * Bdim;
        const float* src = epi + (size_t)(tl * 128 + h) * EPI_STR;
#pragma unroll
        for (int j = 0; j < 64; j += 4) {
            float4 o;
            o.x = src[j]; o.y = src[j + 1]; o.z = src[j + 2]; o.w = src[j + 3];
            *reinterpret_cast<float4*>(dst + j) = o;
        }
    }
}

// ---------------------------------------------------------------------------
// LIF scan: one warp per h, lanes own b = 2*lane, 2*lane+1.
// 8-deep rotating prefetch (covers full L2 latency); ballot+popc exact sum.
// ---------------------------------------------------------------------------
__global__ __launch_bounds__(256) void scan_kernel(
    const float* __restrict__ threshold,
    const float* __restrict__ p_tau_mem, const float* __restrict__ p_tau_syn,
    const float* __restrict__ p_target,  const float* __restrict__ p_lr,
    float* __restrict__ out)
{
    int tid  = threadIdx.x;
    int lane = tid & 31;
    int h    = blockIdx.x * 8 + (tid >> 5);

    float tau_m = *p_tau_mem, tau_s = *p_tau_syn;
    float a_mem = (float)exp(-(double)(0.001f / tau_m));
    float a_syn = (float)exp(-(double)(0.001f / tau_s));
    float target = *p_target, lr = *p_lr;

    float thr = threshold[h];
    float fre = 0.0f;
    float isyn0 = 0.0f, v0 = 0.0f, isyn1 = 0.0f, v1 = 0.0f;
    unsigned sb0[4] = {0u, 0u, 0u, 0u};
    unsigned sb1[4] = {0u, 0u, 0u, 0u};

    const float* wptr = g_weightedT + (size_t)h * Bdim + lane * 2;
    const size_t TSTR = (size_t)Hdim * Bdim;

    float2 wbuf[8];
#pragma unroll
    for (int p = 0; p < 8; p++)
        wbuf[p] = *reinterpret_cast<const float2*>(wptr + p * TSTR);

#pragma unroll 8
    for (int t = 0; t < Tdim; ++t) {
        float2 w = wbuf[t & 7];
        if (t + 8 < Tdim)
            wbuf[t & 7] = *reinterpret_cast<const float2*>(wptr + (size_t)(t + 8) * TSTR);

        isyn0 = fmaf(a_syn, isyn0, w.x);
        v0    = fmaf(a_mem, v0, isyn0);
        isyn1 = fmaf(a_syn, isyn1, w.y);
        v1    = fmaf(a_mem, v1, isyn1);
        bool p0 = (v0 >= thr), p1 = (v1 >= thr);
        if (p0) { v0 -= thr; sb0[t >> 5] |= (1u << (t & 31)); }
        if (p1) { v1 -= thr; sb1[t >> 5] |= (1u << (t & 31)); }

        unsigned m0 = __ballot_sync(0xffffffffu, p0);
        unsigned m1 = __ballot_sync(0xffffffffu, p1);
        float s = (float)(__popc(m0) + __popc(m1));      // exact int

        float rate = s * (1.0f / 64.0f);
        fre = 0.99f * fre + 0.01f * rate;
        thr = thr + lr * (fre - target);
    }

    int bsel = (lane & 7) * 4;
#pragma unroll 4
    for (int bb = 0; bb < 64; ++bb) {
        int src = bb >> 1;
        unsigned w0, w1, w2, w3;
        if (bb & 1) {
            w0 = __shfl_sync(0xffffffffu, sb1[0], src);
            w1 = __shfl_sync(0xffffffffu, sb1[1], src);
            w2 = __shfl_sync(0xffffffffu, sb1[2], src);
            w3 = __shfl_sync(0xffffffffu, sb1[3], src);
        } else {
            w0 = __shfl_sync(0xffffffffu, sb0[0], src);
            w1 = __shfl_sync(0xffffffffu, sb0[1], src);
            w2 = __shfl_sync(0xffffffffu, sb0[2], src);
            w3 = __shfl_sync(0xffffffffu, sb0[3], src);
        }
        unsigned wsel = (lane < 8) ? w0 : (lane < 16) ? w1 : (lane < 24) ? w2 : w3;
        unsigned bits = (wsel >> bsel) & 0xFu;
        float4 o;
        o.x = (float)(bits & 1u);
        o.y = (float)((bits >> 1) & 1u);
        o.z = (float)((bits >> 2) & 1u);
        o.w = (float)((bits >> 3) & 1u);
        *reinterpret_cast<float4*>(
            out + ((size_t)bb * Hdim + h) * Tdim + lane * 4) = o;
    }
}

// ---------------------------------------------------------------------------
extern "C" void kernel_launch(void* const* d_in, const int* in_sizes, int n_in,
                              void* d_out, int out_size) {
    const float* spikes    = (const float*)d_in[0];
    const float* weight    = (const float*)d_in[1];
    const float* strength  = (const float*)d_in[2];
    const float* threshold = (const float*)d_in[3];
    const float* tau_mem   = (const float*)d_in[4];
    const float* tau_syn   = (const float*)d_in[5];
    const float* target    = (const float*)d_in[6];
    const float* lr        = (const float*)d_in[7];
    float* out = (float*)d_out;

    cudaFuncSetAttribute(gemm_mma_kernel,
                         cudaFuncAttributeMaxDynamicSharedMemorySize, GEMM_SMEM);

    prep_kernel<<<10240, dim3(32, 8)>>>(spikes, weight, strength);
    gemm_mma_kernel<<<dim3(Hdim / BN, Mtot / BM), 256, GEMM_SMEM>>>();
    scan_kernel<<<Hdim / 8, 256>>>(threshold, tau_mem, tau_syn, target, lr, out);
}